// round 2
// baseline (speedup 1.0000x reference)
#include <cuda_runtime.h>
#include <cuda_bf16.h>
#include <cstdint>

#define NN 50000
#define EE 600000
#define CC 128

// Scratch (device globals — no runtime allocation allowed)
__device__ float        g_xw[NN * CC];
__device__ float        g_agg[NN * CC];
__device__ float        g_dinv[NN];
__device__ unsigned int g_deg[NN];

// ---------------------------------------------------------------------------
// K0: zero degree counters
// ---------------------------------------------------------------------------
__global__ void k_zero_deg(int n) {
    int i = blockIdx.x * blockDim.x + threadIdx.x;
    if (i < n) g_deg[i] = 0u;
}

// ---------------------------------------------------------------------------
// K1: degree histogram over dst
// ---------------------------------------------------------------------------
__global__ void k_count(const int* __restrict__ ei, int E) {
    int e = blockIdx.x * blockDim.x + threadIdx.x;
    if (e < E) atomicAdd(&g_deg[ei[E + e]], 1u);
}

// ---------------------------------------------------------------------------
// K2: xw = x @ W   (fp32, 64-row x 128-col tile per block, k-chunked smem)
// ---------------------------------------------------------------------------
__global__ __launch_bounds__(256) void k_gemm(const float* __restrict__ x,
                                              const float* __restrict__ W,
                                              int n) {
    __shared__ float xs[32 * 68];    // [k][row], row-stride 68 (16B-aligned, low conflict)
    __shared__ float ws[32 * 128];   // [k][col]

    const int row0 = blockIdx.x * 64;
    const int t  = threadIdx.x;
    const int tc = t & 15;           // col group: cols [tc*8, tc*8+8)
    const int tr = t >> 4;           // row group: rows [tr*4, tr*4+4)

    float acc[4][8];
#pragma unroll
    for (int i = 0; i < 4; i++)
#pragma unroll
        for (int j = 0; j < 8; j++) acc[i][j] = 0.0f;

    for (int kc = 0; kc < 128; kc += 32) {
        __syncthreads();
        // load x tile (64 rows x 32 k), transposed into xs[k][row]
#pragma unroll
        for (int j = t; j < 512; j += 256) {     // 512 float4 loads
            int r  = j >> 3;
            int k4 = j & 7;
            int row = row0 + r;
            if (row >= n) row = n - 1;           // clamp (stores guarded later)
            float4 v = ((const float4*)x)[row * 32 + (kc >> 2) + k4];
            xs[(k4 * 4 + 0) * 68 + r] = v.x;
            xs[(k4 * 4 + 1) * 68 + r] = v.y;
            xs[(k4 * 4 + 2) * 68 + r] = v.z;
            xs[(k4 * 4 + 3) * 68 + r] = v.w;
        }
        // load W chunk (32 k x 128 cols)
#pragma unroll
        for (int j = t; j < 1024; j += 256) {    // 1024 float4 loads
            ((float4*)ws)[j] = ((const float4*)W)[kc * 32 + j];
        }
        __syncthreads();

#pragma unroll
        for (int k = 0; k < 32; k++) {
            float4 xv = *(const float4*)&xs[k * 68 + tr * 4];
            float4 w0 = *(const float4*)&ws[k * 128 + tc * 8];
            float4 w1 = *(const float4*)&ws[k * 128 + tc * 8 + 4];
            float xr[4] = {xv.x, xv.y, xv.z, xv.w};
            float wv[8] = {w0.x, w0.y, w0.z, w0.w, w1.x, w1.y, w1.z, w1.w};
#pragma unroll
            for (int i = 0; i < 4; i++)
#pragma unroll
                for (int j = 0; j < 8; j++)
                    acc[i][j] = fmaf(xr[i], wv[j], acc[i][j]);
        }
    }

#pragma unroll
    for (int i = 0; i < 4; i++) {
        int row = row0 + tr * 4 + i;
        if (row < n) {
            float4 o0 = make_float4(acc[i][0], acc[i][1], acc[i][2], acc[i][3]);
            float4 o1 = make_float4(acc[i][4], acc[i][5], acc[i][6], acc[i][7]);
            ((float4*)g_xw)[row * 32 + tc * 2]     = o0;
            ((float4*)g_xw)[row * 32 + tc * 2 + 1] = o1;
        }
    }
}

// ---------------------------------------------------------------------------
// K3: per-node dinv + agg init with self-loop term: agg = xw * dinv^2
//     (one warp per node)
// ---------------------------------------------------------------------------
__global__ void k_node_init(int n) {
    int gt   = blockIdx.x * blockDim.x + threadIdx.x;
    int node = gt >> 5;
    int lane = gt & 31;
    if (node >= n) return;
    float deg  = (float)g_deg[node] + 1.0f;
    float dinv = rsqrtf(deg);
    if (lane == 0) g_dinv[node] = dinv;
    float s = dinv * dinv;
    float4 v = ((const float4*)g_xw)[node * 32 + lane];
    v.x *= s; v.y *= s; v.z *= s; v.w *= s;
    ((float4*)g_agg)[node * 32 + lane] = v;
}

// ---------------------------------------------------------------------------
// K4: edge scatter — one warp per edge, vector RED into agg[dst]
// ---------------------------------------------------------------------------
__global__ void k_scatter(const int* __restrict__ ei, int E) {
    int gt   = blockIdx.x * blockDim.x + threadIdx.x;
    int e    = gt >> 5;
    int lane = gt & 31;
    if (e >= E) return;
    int src = __ldg(&ei[e]);
    int dst = __ldg(&ei[E + e]);
    float norm = g_dinv[src] * g_dinv[dst];
    float4 v = ((const float4*)g_xw)[src * 32 + lane];
    v.x *= norm; v.y *= norm; v.z *= norm; v.w *= norm;
    float* p = g_agg + (size_t)dst * CC + lane * 4;
    asm volatile("red.global.add.v4.f32 [%0], {%1, %2, %3, %4};"
                 :: "l"(p), "f"(v.x), "f"(v.y), "f"(v.z), "f"(v.w)
                 : "memory");
}

// ---------------------------------------------------------------------------
// K5: finalize — bias, LayerNorm(C=128), LeakyReLU, residual. One warp/node.
// ---------------------------------------------------------------------------
__global__ void k_finalize(const float* __restrict__ x,
                           const float* __restrict__ b,
                           const float* __restrict__ gamma,
                           const float* __restrict__ beta,
                           float* __restrict__ out, int n) {
    int gt   = blockIdx.x * blockDim.x + threadIdx.x;
    int node = gt >> 5;
    int lane = gt & 31;
    if (node >= n) return;

    float4 v  = ((const float4*)g_agg)[node * 32 + lane];
    float4 bv = ((const float4*)b)[lane];
    v.x += bv.x; v.y += bv.y; v.z += bv.z; v.w += bv.w;

    float sum = v.x + v.y + v.z + v.w;
#pragma unroll
    for (int off = 16; off > 0; off >>= 1)
        sum += __shfl_xor_sync(0xffffffffu, sum, off);
    float mean = sum * (1.0f / 128.0f);

    float cx = v.x - mean, cy = v.y - mean, cz = v.z - mean, cw = v.w - mean;
    float sq = cx * cx + cy * cy + cz * cz + cw * cw;
#pragma unroll
    for (int off = 16; off > 0; off >>= 1)
        sq += __shfl_xor_sync(0xffffffffu, sq, off);
    float var  = sq * (1.0f / 128.0f);
    float rstd = rsqrtf(var + 1e-5f);

    float4 g  = ((const float4*)gamma)[lane];
    float4 be = ((const float4*)beta)[lane];
    float4 xr = ((const float4*)x)[node * 32 + lane];

    float4 o;
    o.x = fmaf(cx * rstd, g.x, be.x);
    o.y = fmaf(cy * rstd, g.y, be.y);
    o.z = fmaf(cz * rstd, g.z, be.z);
    o.w = fmaf(cw * rstd, g.w, be.w);
    o.x = (o.x >= 0.0f ? o.x : 0.01f * o.x) + xr.x;
    o.y = (o.y >= 0.0f ? o.y : 0.01f * o.y) + xr.y;
    o.z = (o.z >= 0.0f ? o.z : 0.01f * o.z) + xr.z;
    o.w = (o.w >= 0.0f ? o.w : 0.01f * o.w) + xr.w;

    ((float4*)out)[node * 32 + lane] = o;
}

// ---------------------------------------------------------------------------
// Host launcher (graph-capturable: kernel launches only, default stream)
// ---------------------------------------------------------------------------
extern "C" void kernel_launch(void* const* d_in, const int* in_sizes, int n_in,
                              void* d_out, int out_size) {
    const float* x     = (const float*)d_in[0];
    const int*   ei    = (const int*)d_in[1];
    const float* W     = (const float*)d_in[2];
    const float* b     = (const float*)d_in[3];
    const float* gamma = (const float*)d_in[4];
    const float* beta  = (const float*)d_in[5];
    float* out = (float*)d_out;

    const int n = in_sizes[0] / CC;      // 50000
    const int E = in_sizes[1] / 2;       // 600000

    k_zero_deg<<<(n + 255) / 256, 256>>>(n);
    k_count<<<(E + 255) / 256, 256>>>(ei, E);
    k_gemm<<<(n + 63) / 64, 256>>>(x, W, n);
    k_node_init<<<(n * 32 + 255) / 256, 256>>>(n);
    k_scatter<<<((long long)E * 32 + 255) / 256, 256>>>(ei, E);
    k_finalize<<<(n * 32 + 255) / 256, 256>>>(x, b, gamma, beta, out, n);
}